// round 16
// baseline (speedup 1.0000x reference)
#include <cuda_runtime.h>
#include <cuda_bf16.h>
#include <mma.h>
#include <cstdint>

using namespace nvcuda;

#define BB 128
#define TT 256
#define DD 256
#define UU 1024
#define NN 2048
#define BT 32768   // BB*TT
#define NCTA 128   // persistent grid: 16 n-tiles x 8 k-slices
#define SAP 136    // padded row stride (elems) for 128-wide tiles
#define SXP 72     // padded row stride for 64-wide tiles

// single dynamic smem symbol for the whole TU
extern __shared__ __align__(1024) char dynsmem[];

// ---------------- device scratch (static, no runtime alloc) ----------------
__device__ float g_P[(size_t)BT * NN];                       // 256 MB  X@Wx
__device__ __nv_bfloat16 g_Xhi[(size_t)BT * DD];
__device__ __nv_bfloat16 g_Xlo[(size_t)BT * DD];
__device__ __nv_bfloat16 g_Wxhi[DD * NN];
__device__ __nv_bfloat16 g_Wxlo[DD * NN];
__device__ __nv_bfloat16 g_Whhi[UU * NN];
__device__ __nv_bfloat16 g_Whlo[UU * NN];
__device__ float g_tau[UU];
__device__ __nv_bfloat16 g_hhi[BB * UU];
__device__ __nv_bfloat16 g_hlo[BB * UU];
__device__ float g_part[8][BB][NN];                          // 8 MB partial sums
// tree barrier state: 16 leaf counters on separate 256B lines + root + gen
__device__ unsigned g_leaf[16 * 64];                         // stride 64 words = 256 B
__device__ unsigned g_root;
__device__ unsigned g_gen;

__device__ __forceinline__ uint32_t smem_u32(const void* p) {
    uint32_t a;
    asm("{ .reg .u64 t; cvta.to.shared.u64 t, %1; cvt.u32.u64 %0, t; }" : "=r"(a) : "l"(p));
    return a;
}

// ---------------- merged prep kernel ----------------
__global__ void prep_kernel(const float* __restrict__ features,
                            const float* __restrict__ Wx,
                            const float* __restrict__ Wh,
                            const float* __restrict__ w_tau,
                            const float* __restrict__ h0) {
    const int gid = blockIdx.x * blockDim.x + threadIdx.x;
    const int stride = gridDim.x * blockDim.x;

    for (int i = gid; i < BT * DD; i += stride) {
        float v = features[i];
        __nv_bfloat16 h = __float2bfloat16(v);
        g_Xhi[i] = h;
        g_Xlo[i] = __float2bfloat16(v - __bfloat162float(h));
    }
    for (int i = gid; i < DD * NN; i += stride) {
        float v = Wx[i];
        __nv_bfloat16 h = __float2bfloat16(v);
        g_Wxhi[i] = h;
        g_Wxlo[i] = __float2bfloat16(v - __bfloat162float(h));
    }
    for (int i = gid; i < UU * NN; i += stride) {
        float v = Wh[i];
        __nv_bfloat16 h = __float2bfloat16(v);
        g_Whhi[i] = h;
        g_Whlo[i] = __float2bfloat16(v - __bfloat162float(h));
    }
    for (int i = gid; i < UU; i += stride) {
        float w = w_tau[i];
        g_tau[i] = log1pf(expf(w));
    }
    for (int i = gid; i < BB * UU; i += stride) {
        float v = h0[i];
        __nv_bfloat16 h = __float2bfloat16(v);
        g_hhi[i] = h;
        g_hlo[i] = __float2bfloat16(v - __bfloat162float(h));
    }
    for (int i = gid; i < 16 * 64; i += stride) g_leaf[i] = 0u;
    if (gid == 0) { g_root = 0u; g_gen = 0u; }
}

// ---------------- precompute GEMM: P = X @ Wx (3x bf16 split, smem-staged) ----
// grid (256, 16): CTA tile 128(M) x 128(N), K=256 in 4 chunks of 64.
__global__ void __launch_bounds__(256) gemm_x_kernel() {
    __nv_bfloat16* smem = (__nv_bfloat16*)dynsmem;
    __nv_bfloat16* sXhi = smem;                       // [128][SXP]
    __nv_bfloat16* sXlo = sXhi + 128 * SXP;           // [128][SXP]
    __nv_bfloat16* sWhi = sXlo + 128 * SXP;           // [64][SAP]
    __nv_bfloat16* sWlo = sWhi + 64 * SAP;            // [64][SAP]

    const int mt = blockIdx.x;
    const int nt = blockIdx.y;
    const int tid = threadIdx.x;
    const int warp = tid >> 5;
    const int wm = warp >> 1;
    const int wn = warp & 1;

    wmma::fragment<wmma::accumulator, 16, 16, 16, float> acc[2][4];
#pragma unroll
    for (int i = 0; i < 2; i++)
#pragma unroll
        for (int j = 0; j < 4; j++) wmma::fill_fragment(acc[i][j], 0.0f);

    for (int ch = 0; ch < 4; ch++) {
        __syncthreads();
        for (int i = tid; i < 1024; i += 256) {
            int row = i >> 3, q = i & 7;
            const uint4* sh = (const uint4*)(g_Xhi + (size_t)(mt * 128 + row) * DD + ch * 64);
            const uint4* sl = (const uint4*)(g_Xlo + (size_t)(mt * 128 + row) * DD + ch * 64);
            ((uint4*)(sXhi + row * SXP))[q] = sh[q];
            ((uint4*)(sXlo + row * SXP))[q] = sl[q];
        }
        for (int i = tid; i < 1024; i += 256) {
            int row = i >> 4, q = i & 15;
            const uint4* sh = (const uint4*)(g_Wxhi + (size_t)(ch * 64 + row) * NN + nt * 128);
            const uint4* sl = (const uint4*)(g_Wxlo + (size_t)(ch * 64 + row) * NN + nt * 128);
            ((uint4*)(sWhi + row * SAP))[q] = sh[q];
            ((uint4*)(sWlo + row * SAP))[q] = sl[q];
        }
        __syncthreads();

        for (int kc = 0; kc < 4; kc++) {
            wmma::fragment<wmma::matrix_a, 16, 16, 16, __nv_bfloat16, wmma::row_major> ahi[2], alo[2];
#pragma unroll
            for (int m = 0; m < 2; m++) {
                wmma::load_matrix_sync(ahi[m], sXhi + (wm * 32 + m * 16) * SXP + kc * 16, SXP);
                wmma::load_matrix_sync(alo[m], sXlo + (wm * 32 + m * 16) * SXP + kc * 16, SXP);
            }
#pragma unroll
            for (int n = 0; n < 4; n++) {
                wmma::fragment<wmma::matrix_b, 16, 16, 16, __nv_bfloat16, wmma::row_major> bhi, blo;
                wmma::load_matrix_sync(bhi, sWhi + (kc * 16) * SAP + wn * 64 + n * 16, SAP);
                wmma::load_matrix_sync(blo, sWlo + (kc * 16) * SAP + wn * 64 + n * 16, SAP);
#pragma unroll
                for (int m = 0; m < 2; m++) {
                    wmma::mma_sync(acc[m][n], ahi[m], bhi, acc[m][n]);
                    wmma::mma_sync(acc[m][n], ahi[m], blo, acc[m][n]);
                    wmma::mma_sync(acc[m][n], alo[m], bhi, acc[m][n]);
                }
            }
        }
    }
#pragma unroll
    for (int m = 0; m < 2; m++)
#pragma unroll
        for (int n = 0; n < 4; n++) {
            float* pd = g_P + (size_t)(mt * 128 + wm * 32 + m * 16) * NN + nt * 128 + wn * 64 + n * 16;
            wmma::store_matrix_sync(pd, acc[m][n], NN, wmma::mem_row_major);
        }
}

// ---------------- tree grid barrier (16 leaves x 8 + root, monotonic) -------
__device__ __forceinline__ void bar_arrive(int c, unsigned target) {
    __syncthreads();
    if (threadIdx.x == 0) {
        __threadfence();
        const int leaf = c >> 3;
        unsigned o = atomicAdd(&g_leaf[leaf * 64], 1u);
        if ((o & 7u) == 7u) {                       // 8th arriver of this leaf
            unsigned o2 = atomicAdd(&g_root, 1u);
            if ((o2 & 15u) == 15u) {                // 16th leaf at root
                __threadfence();
                atomicExch(&g_gen, target);
            }
        }
    }
}
__device__ __forceinline__ void bar_wait(unsigned target) {
    if (threadIdx.x == 0) {
        while (*((volatile unsigned*)&g_gen) < target) __nanosleep(32);
        __threadfence();
    }
    __syncthreads();
}

// ---------------- persistent recurrence kernel ----------------
// CTA c: n-tile = c & 15 (128 output cols), k-slice = c >> 4 (128 K).
// Warp w owns 16-col strip. Resident B: 16 frags. h row c in registers.
__global__ void __launch_bounds__(256, 1) rnn_persist_kernel(
    const float* __restrict__ ts,      // [B,T]
    const float* __restrict__ bias,    // [2U]
    const float* __restrict__ h0,      // [B,U]
    float* __restrict__ out)           // [B,T,U]
{
    __nv_bfloat16* sm0 = (__nv_bfloat16*)dynsmem;               // [128][SAP]
    __nv_bfloat16* sm1 = (__nv_bfloat16*)(dynsmem + 34816);     // [128][SAP]
    float* s_ts = (float*)(dynsmem + 69632);                    // [TT]

    const int c = blockIdx.x;
    const int n = c & 15;
    const int ks = c >> 4;
    const int tid = threadIdx.x;
    const int warp = tid >> 5;
    const int u0 = tid * 4;

    // ---- one-time: stage Wh tile, load resident B fragments, ts row ----
    for (int i = tid; i < 2048; i += 256) {
        int row = i >> 4, q = i & 15;
        const uint4* sh = (const uint4*)(g_Whhi + (size_t)(ks * 128 + row) * NN + n * 128);
        const uint4* sl = (const uint4*)(g_Whlo + (size_t)(ks * 128 + row) * NN + n * 128);
        ((uint4*)(sm0 + row * SAP))[q] = sh[q];
        ((uint4*)(sm1 + row * SAP))[q] = sl[q];
    }
    for (int i = tid; i < TT; i += 256) s_ts[i] = ts[c * TT + i];
    __syncthreads();

    wmma::fragment<wmma::matrix_b, 16, 16, 16, __nv_bfloat16, wmma::row_major> Bhi[8], Blo[8];
#pragma unroll
    for (int kc = 0; kc < 8; kc++) {
        wmma::load_matrix_sync(Bhi[kc], sm0 + (kc * 16) * SAP + warp * 16, SAP);
        wmma::load_matrix_sync(Blo[kc], sm1 + (kc * 16) * SAP + warp * 16, SAP);
    }
    __syncthreads();   // all warps done reading before smem reuse

    // loop-invariant registers
    const float4 bf_c = *(const float4*)&bias[u0];
    const float4 ba_c = *(const float4*)&bias[UU + u0];
    const float4 tu_c = *(const float4*)&g_tau[u0];
    float4 h_reg = *(const float4*)&h0[c * UU + u0];

    wmma::fragment<wmma::accumulator, 16, 16, 16, float> acc[8];

    for (int t = 0; t < TT; t++) {
        // ---- stage h slice: rows = batch 0..127, cols = ks*128 + [0,128) ----
        for (int i = tid; i < 2048; i += 256) {
            int row = i >> 4, q = i & 15;
            ((uint4*)(sm0 + row * SAP))[q] =
                __ldcg(((const uint4*)(g_hhi + (size_t)row * UU + ks * 128)) + q);
            ((uint4*)(sm1 + row * SAP))[q] =
                __ldcg(((const uint4*)(g_hlo + (size_t)row * UU + ks * 128)) + q);
        }
        __syncthreads();

        // ---- partial GEMM: h_slice @ Wh_tile ----
#pragma unroll
        for (int m = 0; m < 8; m++) wmma::fill_fragment(acc[m], 0.0f);
#pragma unroll
        for (int kc = 0; kc < 8; kc++) {
#pragma unroll
            for (int m = 0; m < 8; m++) {
                wmma::fragment<wmma::matrix_a, 16, 16, 16, __nv_bfloat16, wmma::row_major> ahi, alo;
                wmma::load_matrix_sync(ahi, sm0 + (m * 16) * SAP + kc * 16, SAP);
                wmma::load_matrix_sync(alo, sm1 + (m * 16) * SAP + kc * 16, SAP);
                wmma::mma_sync(acc[m], ahi, Bhi[kc], acc[m]);
                wmma::mma_sync(acc[m], ahi, Blo[kc], acc[m]);
                wmma::mma_sync(acc[m], alo, Bhi[kc], acc[m]);
            }
        }
#pragma unroll
        for (int m = 0; m < 8; m++) {
            float* pd = &g_part[ks][m * 16][n * 128 + warp * 16];
            wmma::store_matrix_sync(pd, acc[m], NN, wmma::mem_row_major);
        }

        // ---- barrier 1 (tree) with P/dt prefetch hidden in the wait ----
        const unsigned e1 = 2u * t + 1u;
        bar_arrive(c, e1);
        const int r = c * TT + t;
        const float4 Pf = *(const float4*)&g_P[(size_t)r * NN + u0];
        const float4 Pa = *(const float4*)&g_P[(size_t)r * NN + UU + u0];
        const float dt = s_ts[t];
        bar_wait(e1);

        // ---- reduce + LTC cell update; CTA c handles batch row b=c ----
        {
            float4 sf = make_float4(0.f, 0.f, 0.f, 0.f);
            float4 sa = make_float4(0.f, 0.f, 0.f, 0.f);
#pragma unroll
            for (int k2 = 0; k2 < 8; k2++) {
                float4 vf = __ldcg((const float4*)&g_part[k2][c][u0]);
                float4 va = __ldcg((const float4*)&g_part[k2][c][UU + u0]);
                sf.x += vf.x; sf.y += vf.y; sf.z += vf.z; sf.w += vf.w;
                sa.x += va.x; sa.y += va.y; sa.z += va.z; sa.w += va.w;
            }

            float hn[4];
#pragma unroll
            for (int j = 0; j < 4; j++) {
                float pf = ((const float*)&sf)[j] + ((const float*)&Pf)[j] + ((const float*)&bf_c)[j];
                float pa = ((const float*)&sa)[j] + ((const float*)&Pa)[j] + ((const float*)&ba_c)[j];
                float f = __fdividef(1.f, 1.f + __expf(-pf));
                float a = 1.f - __fdividef(2.f, __expf(2.f * pa) + 1.f);   // tanh
                float dec = __expf(-dt * (((const float*)&tu_c)[j] + f));
                float ho = ((const float*)&h_reg)[j];
                hn[j] = (ho - a) * dec + a;
            }
            h_reg = make_float4(hn[0], hn[1], hn[2], hn[3]);

            *(float4*)&out[(size_t)c * TT * UU + (size_t)t * UU + u0] = h_reg;

            __nv_bfloat16 hi[4], lo[4];
#pragma unroll
            for (int j = 0; j < 4; j++) {
                hi[j] = __float2bfloat16(hn[j]);
                lo[j] = __float2bfloat16(hn[j] - __bfloat162float(hi[j]));
            }
            *(uint2*)&g_hhi[c * UU + u0] = *(const uint2*)hi;
            *(uint2*)&g_hlo[c * UU + u0] = *(const uint2*)lo;
        }

        // ---- barrier 2 (tree; h published before next step's staging) ----
        const unsigned e2 = 2u * t + 2u;
        bar_arrive(c, e2);
        bar_wait(e2);
    }
}

// ---------------- launch ----------------
extern "C" void kernel_launch(void* const* d_in, const int* in_sizes, int n_in,
                              void* d_out, int out_size) {
    const float* features   = (const float*)d_in[0];
    const float* time_steps = (const float*)d_in[1];
    const float* Wx         = (const float*)d_in[2];
    const float* Wh         = (const float*)d_in[3];
    const float* bias       = (const float*)d_in[4];
    const float* w_tau      = (const float*)d_in[5];
    const float* h0         = (const float*)d_in[6];
    float* out = (float*)d_out;

    const int smem_gemm = (2 * 128 * SXP + 2 * 64 * SAP) * 2;        // 71,680 B
    const int smem_rnn  = 2 * 128 * SAP * 2 + TT * 4;                // 70,656 B
    cudaFuncSetAttribute(gemm_x_kernel,
                         cudaFuncAttributeMaxDynamicSharedMemorySize, smem_gemm);
    cudaFuncSetAttribute(rnn_persist_kernel,
                         cudaFuncAttributeMaxDynamicSharedMemorySize, smem_rnn);

    // 1) merged prep: splits + tau + h init + barrier reset
    prep_kernel<<<2048, 256>>>(features, Wx, Wh, w_tau, h0);

    // 2) precompute P = X @ Wx
    {
        dim3 grid(BT / 128, NN / 128);
        gemm_x_kernel<<<grid, 256, smem_gemm>>>();
    }

    // 3) persistent sequential scan
    rnn_persist_kernel<<<NCTA, 256, smem_rnn>>>(time_steps, bias, h0, out);
}

// round 17
// speedup vs baseline: 1.0096x; 1.0096x over previous
#include <cuda_runtime.h>
#include <cuda_bf16.h>
#include <mma.h>
#include <cstdint>

using namespace nvcuda;

#define BB 128
#define TT 256
#define DD 256
#define UU 1024
#define NN 2048
#define BT 32768   // BB*TT
#define NCTA 128   // 16 n-tiles x 8 k-slices
#define SAP 136    // padded row stride (elems) for 128-wide tiles
#define SXP 72     // padded row stride for 64-wide tiles

// single dynamic smem symbol for the whole TU
extern __shared__ __align__(1024) char dynsmem[];

// ---------------- device scratch (static, no runtime alloc) ----------------
__device__ float g_P[(size_t)BT * NN];                       // 256 MB  X@Wx
__device__ __nv_bfloat16 g_Xhi[(size_t)BT * DD];
__device__ __nv_bfloat16 g_Xlo[(size_t)BT * DD];
__device__ __nv_bfloat16 g_Wxhi[DD * NN];
__device__ __nv_bfloat16 g_Wxlo[DD * NN];
__device__ __nv_bfloat16 g_Whhi[(size_t)UU * NN];            // PERMUTED columns
__device__ __nv_bfloat16 g_Whlo[(size_t)UU * NN];
__device__ float g_tau[UU];
__device__ __nv_bfloat16 g_hhi[BB * UU];
__device__ __nv_bfloat16 g_hlo[BB * UU];
__device__ float g_part[8][BB][NN];                          // [ks][row][permuted col]
// dataflow flags: monotonic step counters, one 128B line per CTA
__device__ unsigned g_flagP[NCTA * 32];   // partials stored
__device__ unsigned g_flagH[NCTA * 32];   // h published
__device__ unsigned g_flagS[NCTA * 32];   // h staged (read-ack)
__device__ unsigned g_flagR[NCTA * 32];   // partials read (read-ack)

__device__ __forceinline__ void spin_ge(volatile unsigned* f, unsigned tgt) {
    while (*f < tgt) __nanosleep(20);
}

// ---------------- merged prep kernel ----------------
__global__ void prep_kernel(const float* __restrict__ features,
                            const float* __restrict__ Wx,
                            const float* __restrict__ Wh,
                            const float* __restrict__ w_tau,
                            const float* __restrict__ h0) {
    const int gid = blockIdx.x * blockDim.x + threadIdx.x;
    const int stride = gridDim.x * blockDim.x;

    for (int i = gid; i < BT * DD; i += stride) {
        float v = features[i];
        __nv_bfloat16 h = __float2bfloat16(v);
        g_Xhi[i] = h;
        g_Xlo[i] = __float2bfloat16(v - __bfloat162float(h));
    }
    for (int i = gid; i < DD * NN; i += stride) {
        float v = Wx[i];
        __nv_bfloat16 h = __float2bfloat16(v);
        g_Wxhi[i] = h;
        g_Wxlo[i] = __float2bfloat16(v - __bfloat162float(h));
    }
    // Wh with permuted columns: dest tile n holds [n*64, n*64+64) (f) then
    // [1024+n*64, 1024+n*64+64) (a)
    for (int i = gid; i < UU * NN; i += stride) {
        int row = i >> 11, jj = i & 2047;
        int nt = jj >> 7, q = jj & 127;
        int src = (q < 64) ? (nt * 64 + q) : (1024 + nt * 64 + (q - 64));
        float v = Wh[(size_t)row * NN + src];
        __nv_bfloat16 h = __float2bfloat16(v);
        g_Whhi[i] = h;
        g_Whlo[i] = __float2bfloat16(v - __bfloat162float(h));
    }
    for (int i = gid; i < UU; i += stride) {
        float w = w_tau[i];
        g_tau[i] = log1pf(expf(w));
    }
    for (int i = gid; i < BB * UU; i += stride) {
        float v = h0[i];
        __nv_bfloat16 h = __float2bfloat16(v);
        g_hhi[i] = h;
        g_hlo[i] = __float2bfloat16(v - __bfloat162float(h));
    }
    for (int i = gid; i < NCTA * 32; i += stride) {
        g_flagP[i] = 0u; g_flagH[i] = 0u; g_flagS[i] = 0u; g_flagR[i] = 0u;
    }
}

// ---------------- precompute GEMM: P = X @ Wx (3x bf16 split, smem-staged) ----
__global__ void __launch_bounds__(256) gemm_x_kernel() {
    __nv_bfloat16* smem = (__nv_bfloat16*)dynsmem;
    __nv_bfloat16* sXhi = smem;                       // [128][SXP]
    __nv_bfloat16* sXlo = sXhi + 128 * SXP;           // [128][SXP]
    __nv_bfloat16* sWhi = sXlo + 128 * SXP;           // [64][SAP]
    __nv_bfloat16* sWlo = sWhi + 64 * SAP;            // [64][SAP]

    const int mt = blockIdx.x;
    const int nt = blockIdx.y;
    const int tid = threadIdx.x;
    const int warp = tid >> 5;
    const int wm = warp >> 1;
    const int wn = warp & 1;

    wmma::fragment<wmma::accumulator, 16, 16, 16, float> acc[2][4];
#pragma unroll
    for (int i = 0; i < 2; i++)
#pragma unroll
        for (int j = 0; j < 4; j++) wmma::fill_fragment(acc[i][j], 0.0f);

    for (int ch = 0; ch < 4; ch++) {
        __syncthreads();
        for (int i = tid; i < 1024; i += 256) {
            int row = i >> 3, q = i & 7;
            const uint4* sh = (const uint4*)(g_Xhi + (size_t)(mt * 128 + row) * DD + ch * 64);
            const uint4* sl = (const uint4*)(g_Xlo + (size_t)(mt * 128 + row) * DD + ch * 64);
            ((uint4*)(sXhi + row * SXP))[q] = sh[q];
            ((uint4*)(sXlo + row * SXP))[q] = sl[q];
        }
        for (int i = tid; i < 1024; i += 256) {
            int row = i >> 4, q = i & 15;
            const uint4* sh = (const uint4*)(g_Wxhi + (size_t)(ch * 64 + row) * NN + nt * 128);
            const uint4* sl = (const uint4*)(g_Wxlo + (size_t)(ch * 64 + row) * NN + nt * 128);
            ((uint4*)(sWhi + row * SAP))[q] = sh[q];
            ((uint4*)(sWlo + row * SAP))[q] = sl[q];
        }
        __syncthreads();

        for (int kc = 0; kc < 4; kc++) {
            wmma::fragment<wmma::matrix_a, 16, 16, 16, __nv_bfloat16, wmma::row_major> ahi[2], alo[2];
#pragma unroll
            for (int m = 0; m < 2; m++) {
                wmma::load_matrix_sync(ahi[m], sXhi + (wm * 32 + m * 16) * SXP + kc * 16, SXP);
                wmma::load_matrix_sync(alo[m], sXlo + (wm * 32 + m * 16) * SXP + kc * 16, SXP);
            }
#pragma unroll
            for (int n = 0; n < 4; n++) {
                wmma::fragment<wmma::matrix_b, 16, 16, 16, __nv_bfloat16, wmma::row_major> bhi, blo;
                wmma::load_matrix_sync(bhi, sWhi + (kc * 16) * SAP + wn * 64 + n * 16, SAP);
                wmma::load_matrix_sync(blo, sWlo + (kc * 16) * SAP + wn * 64 + n * 16, SAP);
#pragma unroll
                for (int m = 0; m < 2; m++) {
                    wmma::mma_sync(acc[m][n], ahi[m], bhi, acc[m][n]);
                    wmma::mma_sync(acc[m][n], ahi[m], blo, acc[m][n]);
                    wmma::mma_sync(acc[m][n], alo[m], bhi, acc[m][n]);
                }
            }
        }
    }
#pragma unroll
    for (int m = 0; m < 2; m++)
#pragma unroll
        for (int n = 0; n < 4; n++) {
            float* pd = g_P + (size_t)(mt * 128 + wm * 32 + m * 16) * NN + nt * 128 + wn * 64 + n * 16;
            wmma::store_matrix_sync(pd, acc[m][n], NN, wmma::mem_row_major);
        }
}

// ---------------- persistent recurrence kernel (dataflow flags) ------------
// CTA c: n = c & 15 (permuted col tile: 64 f + 64 a units [n*64,+64)),
//        ks = c >> 4 (K-slice rows [ks*128,+128); epilogue rows [ks*16,+16)).
__global__ void __launch_bounds__(256, 1) rnn_persist_kernel(
    const float* __restrict__ ts,      // [B,T]
    const float* __restrict__ bias,    // [2U]
    const float* __restrict__ h0,      // [B,U]
    float* __restrict__ out)           // [B,T,U]
{
    __nv_bfloat16* sm0 = (__nv_bfloat16*)dynsmem;               // [128][SAP]
    __nv_bfloat16* sm1 = (__nv_bfloat16*)(dynsmem + 34816);     // [128][SAP]
    float* s_ts = (float*)(dynsmem + 69632);                    // [16][TT]

    const int c = blockIdx.x;
    const int n = c & 15;
    const int ks = c >> 4;
    const int tid = threadIdx.x;
    const int warp = tid >> 5;

    // epilogue cell ownership: row erow, 4 units u0 (in permuted-unit space)
    const int erow = ks * 16 + (tid >> 4);
    const int qf = (tid & 15) * 4;            // 0..63 within tile's f-half
    const int u0 = n * 64 + qf;               // global unit index

    // ---- one-time: stage permuted Wh tile, resident B fragments, ts rows ----
    for (int i = tid; i < 2048; i += 256) {
        int row = i >> 4, q = i & 15;
        const uint4* sh = (const uint4*)(g_Whhi + (size_t)(ks * 128 + row) * NN + n * 128);
        const uint4* sl = (const uint4*)(g_Whlo + (size_t)(ks * 128 + row) * NN + n * 128);
        ((uint4*)(sm0 + row * SAP))[q] = sh[q];
        ((uint4*)(sm1 + row * SAP))[q] = sl[q];
    }
    for (int i = tid; i < 16 * TT; i += 256) {
        int g = i >> 8, t = i & 255;
        s_ts[g * TT + t] = ts[(ks * 16 + g) * TT + t];
    }
    __syncthreads();

    wmma::fragment<wmma::matrix_b, 16, 16, 16, __nv_bfloat16, wmma::row_major> Bhi[8], Blo[8];
#pragma unroll
    for (int kc = 0; kc < 8; kc++) {
        wmma::load_matrix_sync(Bhi[kc], sm0 + (kc * 16) * SAP + warp * 16, SAP);
        wmma::load_matrix_sync(Blo[kc], sm1 + (kc * 16) * SAP + warp * 16, SAP);
    }
    __syncthreads();   // all warps done reading before smem reuse

    // loop-invariant registers (4 units of one row, owned forever)
    const float4 bf_c = *(const float4*)&bias[u0];
    const float4 ba_c = *(const float4*)&bias[UU + u0];
    const float4 tu_c = *(const float4*)&g_tau[u0];
    float4 h_reg = *(const float4*)&h0[erow * UU + u0];

    wmma::fragment<wmma::accumulator, 16, 16, 16, float> acc[8];

    for (int t = 0; t < TT; t++) {
        // ---- W1: wait h producers (units [ks*128,+128) -> n' in {2ks,2ks+1}) ----
        if (tid < 16) {
            int p = ((tid & 7) << 4) | (ks * 2 + (tid >> 3));
            spin_ge(&g_flagH[p * 32], (unsigned)t);
            __threadfence();
        }
        __syncthreads();

        // ---- stage h slice: rows 0..127, unit cols [ks*128,+128) ----
        for (int i = tid; i < 2048; i += 256) {
            int row = i >> 4, q = i & 15;
            ((uint4*)(sm0 + row * SAP))[q] =
                __ldcg(((const uint4*)(g_hhi + (size_t)row * UU + ks * 128)) + q);
            ((uint4*)(sm1 + row * SAP))[q] =
                __ldcg(((const uint4*)(g_hlo + (size_t)row * UU + ks * 128)) + q);
        }
        __syncthreads();
        if (tid == 0) {   // staged-ack (read of h complete)
            __threadfence();
            *(volatile unsigned*)&g_flagS[c * 32] = (unsigned)(t + 1);
        }

        // ---- partial GEMM: h_slice @ Wh_tile (B resident) ----
#pragma unroll
        for (int m = 0; m < 8; m++) wmma::fill_fragment(acc[m], 0.0f);
#pragma unroll
        for (int kc = 0; kc < 8; kc++) {
#pragma unroll
            for (int m = 0; m < 8; m++) {
                wmma::fragment<wmma::matrix_a, 16, 16, 16, __nv_bfloat16, wmma::row_major> ahi, alo;
                wmma::load_matrix_sync(ahi, sm0 + (m * 16) * SAP + kc * 16, SAP);
                wmma::load_matrix_sync(alo, sm1 + (m * 16) * SAP + kc * 16, SAP);
                wmma::mma_sync(acc[m], ahi, Bhi[kc], acc[m]);
                wmma::mma_sync(acc[m], ahi, Blo[kc], acc[m]);
                wmma::mma_sync(acc[m], alo, Bhi[kc], acc[m]);
            }
        }

        // ---- W2: WAR ack — group readers done with step t-1 partials ----
        if (tid < 8) {
            spin_ge(&g_flagR[((tid << 4) | n) * 32], (unsigned)t);
        }
        __syncthreads();
#pragma unroll
        for (int m = 0; m < 8; m++) {
            float* pd = &g_part[ks][m * 16][n * 128 + warp * 16];
            wmma::store_matrix_sync(pd, acc[m], NN, wmma::mem_row_major);
        }
        __threadfence();
        __syncthreads();
        if (tid == 0) *(volatile unsigned*)&g_flagP[c * 32] = (unsigned)(t + 1);

        // ---- prefetch P/dt, then W3: wait group partials ----
        const int r = erow * TT + t;
        const float4 Pf = __ldcg((const float4*)&g_P[(size_t)r * NN + u0]);
        const float4 Pa = __ldcg((const float4*)&g_P[(size_t)r * NN + UU + u0]);
        const float dt = s_ts[(tid >> 4) * TT + t];
        if (tid < 8) {
            spin_ge(&g_flagP[((tid << 4) | n) * 32], (unsigned)(t + 1));
            __threadfence();
        }
        __syncthreads();

        // ---- reduce over 8 k-slices for (erow, units u0..u0+3) ----
        float4 sf = make_float4(0.f, 0.f, 0.f, 0.f);
        float4 sa = make_float4(0.f, 0.f, 0.f, 0.f);
#pragma unroll
        for (int k2 = 0; k2 < 8; k2++) {
            float4 vf = __ldcg((const float4*)&g_part[k2][erow][n * 128 + qf]);
            float4 va = __ldcg((const float4*)&g_part[k2][erow][n * 128 + 64 + qf]);
            sf.x += vf.x; sf.y += vf.y; sf.z += vf.z; sf.w += vf.w;
            sa.x += va.x; sa.y += va.y; sa.z += va.z; sa.w += va.w;
        }
        __syncthreads();
        if (tid == 0) {   // read-ack for partials
            __threadfence();
            *(volatile unsigned*)&g_flagR[c * 32] = (unsigned)(t + 1);
        }

        // ---- LTC cell update ----
        float hn[4];
#pragma unroll
        for (int j = 0; j < 4; j++) {
            float pf = ((const float*)&sf)[j] + ((const float*)&Pf)[j] + ((const float*)&bf_c)[j];
            float pa = ((const float*)&sa)[j] + ((const float*)&Pa)[j] + ((const float*)&ba_c)[j];
            float f = __fdividef(1.f, 1.f + __expf(-pf));
            float a = 1.f - __fdividef(2.f, __expf(2.f * pa) + 1.f);   // tanh
            float dec = __expf(-dt * (((const float*)&tu_c)[j] + f));
            float ho = ((const float*)&h_reg)[j];
            hn[j] = (ho - a) * dec + a;
        }
        h_reg = make_float4(hn[0], hn[1], hn[2], hn[3]);
        *(float4*)&out[(size_t)erow * TT * UU + (size_t)t * UU + u0] = h_reg;

        // ---- W4: WAR ack — consumers staged our old h (stagers ks2 = n>>1) ----
        if (tid < 16) {
            spin_ge(&g_flagS[(((n >> 1) << 4) | tid) * 32], (unsigned)(t + 1));
        }
        __syncthreads();

        // ---- publish h ----
        {
            __nv_bfloat16 hi[4], lo[4];
#pragma unroll
            for (int j = 0; j < 4; j++) {
                hi[j] = __float2bfloat16(hn[j]);
                lo[j] = __float2bfloat16(hn[j] - __bfloat162float(hi[j]));
            }
            *(uint2*)&g_hhi[erow * UU + u0] = *(const uint2*)hi;
            *(uint2*)&g_hlo[erow * UU + u0] = *(const uint2*)lo;
        }
        __threadfence();
        __syncthreads();
        if (tid == 0) *(volatile unsigned*)&g_flagH[c * 32] = (unsigned)(t + 1);
    }
}

// ---------------- launch ----------------
extern "C" void kernel_launch(void* const* d_in, const int* in_sizes, int n_in,
                              void* d_out, int out_size) {
    const float* features   = (const float*)d_in[0];
    const float* time_steps = (const float*)d_in[1];
    const float* Wx         = (const float*)d_in[2];
    const float* Wh         = (const float*)d_in[3];
    const float* bias       = (const float*)d_in[4];
    const float* w_tau      = (const float*)d_in[5];
    const float* h0         = (const float*)d_in[6];
    float* out = (float*)d_out;

    const int smem_gemm = (2 * 128 * SXP + 2 * 64 * SAP) * 2;        // 71,680 B
    const int smem_rnn  = 2 * 128 * SAP * 2 + 16 * TT * 4;           // 86,016 B
    cudaFuncSetAttribute(gemm_x_kernel,
                         cudaFuncAttributeMaxDynamicSharedMemorySize, smem_gemm);
    cudaFuncSetAttribute(rnn_persist_kernel,
                         cudaFuncAttributeMaxDynamicSharedMemorySize, smem_rnn);

    // 1) merged prep: splits + permuted Wh + tau + h init + flag reset
    prep_kernel<<<2048, 256>>>(features, Wx, Wh, w_tau, h0);

    // 2) precompute P = X @ Wx
    {
        dim3 grid(BT / 128, NN / 128);
        gemm_x_kernel<<<grid, 256, smem_gemm>>>();
    }

    // 3) persistent sequential scan with dataflow sync
    rnn_persist_kernel<<<NCTA, 256, smem_rnn>>>(time_steps, bias, h0, out);
}